// round 1
// baseline (speedup 1.0000x reference)
#include <cuda_runtime.h>
#include <math.h>

#define T 2048
#define H 1024
#define FF 512
#define E 16
#define TOPK 4

// ---------------- scratch (static device globals; no runtime allocation) ----
__device__ int   g_cnt[E];
__device__ int   g_list[E * T];        // entry = token*4 + k
__device__ float g_wlist[E * T];       // normalized combine weight
__device__ float g_act[(size_t)E * T * FF];   // 64 MB: per-expert activated rows
__device__ float g_ybuf[(size_t)T * TOPK * H]; // 32 MB: per-(token,k) scaled expert out
__device__ float g_sact[(size_t)T * FF];       // 4 MB: shared-expert activations
__device__ float g_sout[(size_t)T * H];        // 8 MB: shared-expert output

// ---------------- reset ----------------
__global__ void k_reset() {
    if (threadIdx.x < E) g_cnt[threadIdx.x] = 0;
}

// ---------------- gating: logits -> sigmoid -> top-4 -> expert lists --------
__global__ void k_gate(const float* __restrict__ x,
                       const float* __restrict__ gw,
                       const float* __restrict__ bias) {
    int warp = threadIdx.x >> 5;
    int lane = threadIdx.x & 31;
    int t = blockIdx.x * 4 + warp;
    if (t >= T) return;
    __shared__ float sc[4][E];
    const float* xr = x + (size_t)t * H;
    for (int e = 0; e < E; e++) {
        const float* g = gw + (size_t)e * H;
        float p = 0.f;
        for (int h = lane; h < H; h += 32) p += xr[h] * g[h];
        #pragma unroll
        for (int o = 16; o > 0; o >>= 1) p += __shfl_down_sync(0xffffffffu, p, o);
        if (lane == 0) sc[warp][e] = 1.f / (1.f + expf(-p));
    }
    __syncwarp();
    if (lane == 0) {
        float s[E]; bool used[E];
        #pragma unroll
        for (int e = 0; e < E; e++) { s[e] = sc[warp][e]; used[e] = false; }
        int sel[TOPK]; float w[TOPK]; float sum = 0.f;
        for (int k = 0; k < TOPK; k++) {
            float best = -1e30f; int bi = 0;
            for (int e = 0; e < E; e++) {
                float v = s[e] + bias[e];
                if (!used[e] && v > best) { best = v; bi = e; }
            }
            used[bi] = true; sel[k] = bi; w[k] = s[bi]; sum += s[bi];
        }
        float inv = 1.f / fmaxf(sum, 1e-20f);
        for (int k = 0; k < TOPK; k++) {
            int e = sel[k];
            int pos = atomicAdd(&g_cnt[e], 1);
            g_list[e * T + pos]  = t * TOPK + k;
            g_wlist[e * T + pos] = w[k] * inv;
        }
    }
}

// ---------------- GEMM1 + SiLU*u (fused gate/up halves in one K pass) -------
// Tile: 64 rows x 32 FF-cols (=> 64x64 accumulators counting g and u halves).
// grid.x = (T/64) * (FF/32), grid.y = E (routed) or 1 (shared)
__global__ void __launch_bounds__(256) k_gemm1(const float* __restrict__ x,
                                               const float* __restrict__ w1base,
                                               int routed) {
    const int FT = FF / 32;   // 16
    int e  = blockIdx.y;
    int mt = blockIdx.x / FT;
    int ft = blockIdx.x % FT;

    int M; const int* list; const float* W; float* ACT;
    if (routed) {
        M = g_cnt[e];
        list = g_list + e * T;
        W = w1base + (size_t)e * 2 * FF * H;
        ACT = g_act + (size_t)e * T * FF;
    } else {
        M = T; list = nullptr; W = w1base; ACT = g_sact;
    }
    int m0 = mt * 64;
    if (m0 >= M) return;
    int f0 = ft * 32;

    __shared__ float As[16][68];
    __shared__ float Bs[16][68];   // cols 0..31 = gate rows, 32..63 = up rows

    int tid = threadIdx.x;
    int tx = tid & 15, ty = tid >> 4;

    float accg[4][2] = {}, accu[4][2] = {};

    // A tile loader mapping: 64 rows x 16 k-cols, float4 per thread
    int arow = tid >> 2;
    int acol = (tid & 3) * 4;
    bool avalid = (m0 + arow) < M;
    int tok = 0;
    if (avalid) tok = list ? (list[m0 + arow] >> 2) : (m0 + arow);
    const float* Arow = x + (size_t)tok * H;

    // B tile loader: 64 rows (32 gate + 32 up) x 16 k-cols
    int brow = tid >> 2;
    int bcol = (tid & 3) * 4;
    int wrow = (brow < 32) ? (f0 + brow) : (FF + f0 + (brow - 32));
    const float* Brow = W + (size_t)wrow * H;

    for (int k0 = 0; k0 < H; k0 += 16) {
        float4 av = avalid ? *(const float4*)(Arow + k0 + acol)
                           : make_float4(0.f, 0.f, 0.f, 0.f);
        float4 bv = *(const float4*)(Brow + k0 + bcol);
        __syncthreads();
        As[acol + 0][arow] = av.x; As[acol + 1][arow] = av.y;
        As[acol + 2][arow] = av.z; As[acol + 3][arow] = av.w;
        Bs[bcol + 0][brow] = bv.x; Bs[bcol + 1][brow] = bv.y;
        Bs[bcol + 2][brow] = bv.z; Bs[bcol + 3][brow] = bv.w;
        __syncthreads();
        #pragma unroll
        for (int kk = 0; kk < 16; kk++) {
            float4 a4 = *(const float4*)&As[kk][ty * 4];
            float2 bg = *(const float2*)&Bs[kk][tx * 2];
            float2 bu = *(const float2*)&Bs[kk][32 + tx * 2];
            float a[4] = {a4.x, a4.y, a4.z, a4.w};
            #pragma unroll
            for (int i = 0; i < 4; i++) {
                accg[i][0] += a[i] * bg.x;
                accg[i][1] += a[i] * bg.y;
                accu[i][0] += a[i] * bu.x;
                accu[i][1] += a[i] * bu.y;
            }
        }
    }

    #pragma unroll
    for (int i = 0; i < 4; i++) {
        int r = m0 + ty * 4 + i;
        if (r < M) {
            #pragma unroll
            for (int j = 0; j < 2; j++) {
                float g = accg[i][j];
                float u = accu[i][j];
                float act = g / (1.f + expf(-g)) * u;   // silu(g)*u
                ACT[(size_t)r * FF + f0 + tx * 2 + j] = act;
            }
        }
    }
}

// ---------------- GEMM2: y = act @ w2^T, scaled scatter ---------------------
// Tile 64x64x16. grid.x = (T/64)*(H/64), grid.y = E (routed) or 1 (shared)
__global__ void __launch_bounds__(256) k_gemm2(const float* __restrict__ w2base,
                                               int routed) {
    const int NT = H / 64;   // 16
    int e  = blockIdx.y;
    int mt = blockIdx.x / NT;
    int nt = blockIdx.x % NT;

    int M; const int* list; const float* wl; const float* A; const float* W;
    if (routed) {
        M = g_cnt[e];
        list = g_list + e * T;
        wl = g_wlist + e * T;
        A = g_act + (size_t)e * T * FF;
        W = w2base + (size_t)e * H * FF;
    } else {
        M = T; list = nullptr; wl = nullptr; A = g_sact; W = w2base;
    }
    int m0 = mt * 64;
    if (m0 >= M) return;
    int n0 = nt * 64;

    __shared__ float As[16][68];
    __shared__ float Bs[16][68];

    int tid = threadIdx.x;
    int tx = tid & 15, ty = tid >> 4;
    float acc[4][4] = {};

    int lrow = tid >> 2;
    int lcol = (tid & 3) * 4;
    bool avalid = (m0 + lrow) < M;
    const float* Ar = A + (size_t)(m0 + lrow) * FF;
    const float* Br = W + (size_t)(n0 + lrow) * FF;

    for (int k0 = 0; k0 < FF; k0 += 16) {
        float4 av = avalid ? *(const float4*)(Ar + k0 + lcol)
                           : make_float4(0.f, 0.f, 0.f, 0.f);
        float4 bv = *(const float4*)(Br + k0 + lcol);
        __syncthreads();
        As[lcol + 0][lrow] = av.x; As[lcol + 1][lrow] = av.y;
        As[lcol + 2][lrow] = av.z; As[lcol + 3][lrow] = av.w;
        Bs[lcol + 0][lrow] = bv.x; Bs[lcol + 1][lrow] = bv.y;
        Bs[lcol + 2][lrow] = bv.z; Bs[lcol + 3][lrow] = bv.w;
        __syncthreads();
        #pragma unroll
        for (int kk = 0; kk < 16; kk++) {
            float4 a4 = *(const float4*)&As[kk][ty * 4];
            float4 b4 = *(const float4*)&Bs[kk][tx * 4];
            float a[4] = {a4.x, a4.y, a4.z, a4.w};
            float b[4] = {b4.x, b4.y, b4.z, b4.w};
            #pragma unroll
            for (int i = 0; i < 4; i++)
                #pragma unroll
                for (int j = 0; j < 4; j++)
                    acc[i][j] += a[i] * b[j];
        }
    }

    #pragma unroll
    for (int i = 0; i < 4; i++) {
        int r = m0 + ty * 4 + i;
        if (r < M) {
            float scale; float* orow;
            if (routed) {
                int entry = list[r];
                scale = wl[r];
                orow = g_ybuf + (size_t)entry * H;
            } else {
                scale = 1.f;
                orow = g_sout + (size_t)r * H;
            }
            #pragma unroll
            for (int j = 0; j < 4; j++)
                orow[n0 + tx * 4 + j] = scale * acc[i][j];
        }
    }
}

// ---------------- combine: out = shared + sum_k routed contributions --------
__global__ void k_combine(float* __restrict__ out) {
    int idx = blockIdx.x * blockDim.x + threadIdx.x;
    if (idx >= T * H) return;
    int t = idx >> 10;          // H == 1024
    int h = idx & (H - 1);
    const float* yb = g_ybuf + (size_t)t * TOPK * H + h;
    out[idx] = g_sout[idx] + yb[0] + yb[H] + yb[2 * H] + yb[3 * H];
}

// ---------------- launcher --------------------------------------------------
extern "C" void kernel_launch(void* const* d_in, const int* in_sizes, int n_in,
                              void* d_out, int out_size) {
    (void)in_sizes; (void)n_in; (void)out_size;
    const float* x    = (const float*)d_in[0];
    const float* gw   = (const float*)d_in[1];
    const float* bias = (const float*)d_in[2];
    const float* w1   = (const float*)d_in[3];
    const float* w2   = (const float*)d_in[4];
    const float* sw1  = (const float*)d_in[5];
    const float* sw2  = (const float*)d_in[6];
    float* out = (float*)d_out;

    k_reset<<<1, 32>>>();
    k_gate<<<T / 4, 128>>>(x, gw, bias);

    // routed expert FFN (gathered rows per expert)
    k_gemm1<<<dim3((T / 64) * (FF / 32), E), 256>>>(x, w1, 1);
    // shared expert FFN part 1
    k_gemm1<<<dim3((T / 64) * (FF / 32), 1), 256>>>(x, sw1, 0);

    k_gemm2<<<dim3((T / 64) * (H / 64), E), 256>>>(w2, 1);
    k_gemm2<<<dim3((T / 64) * (H / 64), 1), 256>>>(sw2, 0);

    k_combine<<<(T * H + 255) / 256, 256>>>(out);
}

// round 3
// speedup vs baseline: 1.8965x; 1.8965x over previous
#include <cuda_runtime.h>
#include <cuda_bf16.h>
#include <math.h>
#include <stdint.h>

#define T 2048
#define H 1024
#define FF 512
#define E 16
#define TOPK 4

// smem tile geometry: A 128 rows x 32 k (bf16), stride 80B; B 64 rows x 32 k
#define ASTRIDE 80
#define A_BYTES (128 * ASTRIDE)      // 10240
#define B_BYTES (64 * ASTRIDE)       // 5120
#define OFF_AHI 0
#define OFF_ALO A_BYTES
#define OFF_BHI (2 * A_BYTES)
#define OFF_BLO (2 * A_BYTES + B_BYTES)
#define SMEM_TOTAL (2 * A_BYTES + 2 * B_BYTES)   // 30720

// ---------------- scratch (static device globals) ---------------------------
__device__ int   g_cnt[E];
__device__ int   g_list[E * T];                 // entry = token*4 + k
__device__ float g_wlist[E * T];                // normalized combine weight
__device__ float g_act[(size_t)E * T * FF];     // per-expert activated rows
__device__ float g_ybuf[(size_t)T * TOPK * H];  // per-(token,k) scaled expert out
__device__ float g_sact[(size_t)T * FF];
__device__ float g_sout[(size_t)T * H];

// ---------------- helpers ----------------------------------------------------
__device__ __forceinline__ uint32_t smem_u32(const void* p) {
    uint32_t a;
    asm("{ .reg .u64 t; cvta.to.shared.u64 t, %1; cvt.u32.u64 %0, t; }"
        : "=r"(a) : "l"(p));
    return a;
}
__device__ __forceinline__ void ldm_x4(uint32_t& r0, uint32_t& r1,
                                       uint32_t& r2, uint32_t& r3, uint32_t a) {
    asm volatile("ldmatrix.sync.aligned.m8n8.x4.shared.b16 {%0,%1,%2,%3}, [%4];"
                 : "=r"(r0), "=r"(r1), "=r"(r2), "=r"(r3) : "r"(a));
}
__device__ __forceinline__ void mma_bf16(float* c, const uint32_t* a, const uint32_t* b) {
    asm volatile(
        "mma.sync.aligned.m16n8k16.row.col.f32.bf16.bf16.f32 "
        "{%0,%1,%2,%3}, {%4,%5,%6,%7}, {%8,%9}, {%0,%1,%2,%3};"
        : "+f"(c[0]), "+f"(c[1]), "+f"(c[2]), "+f"(c[3])
        : "r"(a[0]), "r"(a[1]), "r"(a[2]), "r"(a[3]), "r"(b[0]), "r"(b[1]));
}
__device__ __forceinline__ uint32_t pk(__nv_bfloat16 a, __nv_bfloat16 b) {
    __nv_bfloat162 t; t.x = a; t.y = b;
    return *reinterpret_cast<uint32_t*>(&t);
}
// split fp32 float4 -> bf16 hi/lo, store 4 elements starting at (row, k)
__device__ __forceinline__ void store_pair(char* hi, char* lo, int row, int k, float4 v) {
    __nv_bfloat16 hx = __float2bfloat16(v.x), hy = __float2bfloat16(v.y);
    __nv_bfloat16 hz = __float2bfloat16(v.z), hw = __float2bfloat16(v.w);
    __nv_bfloat16 lx = __float2bfloat16(v.x - __bfloat162float(hx));
    __nv_bfloat16 ly = __float2bfloat16(v.y - __bfloat162float(hy));
    __nv_bfloat16 lz = __float2bfloat16(v.z - __bfloat162float(hz));
    __nv_bfloat16 lw = __float2bfloat16(v.w - __bfloat162float(hw));
    uint32_t off = row * ASTRIDE + k * 2;
    *(uint32_t*)(hi + off)     = pk(hx, hy);
    *(uint32_t*)(hi + off + 4) = pk(hz, hw);
    *(uint32_t*)(lo + off)     = pk(lx, ly);
    *(uint32_t*)(lo + off + 4) = pk(lz, lw);
}
__device__ __forceinline__ float silu_mul(float g, float u) {
    return g / (1.f + expf(-g)) * u;
}

// ---------------- reset ------------------------------------------------------
__global__ void k_reset() {
    if (threadIdx.x < E) g_cnt[threadIdx.x] = 0;
}

// ---------------- gating -----------------------------------------------------
__global__ void k_gate(const float* __restrict__ x,
                       const float* __restrict__ gw,
                       const float* __restrict__ bias) {
    int warp = threadIdx.x >> 5;
    int lane = threadIdx.x & 31;
    int t = blockIdx.x * 4 + warp;
    if (t >= T) return;
    __shared__ float sc[4][E];
    const float* xr = x + (size_t)t * H;
    for (int e = 0; e < E; e++) {
        const float* g = gw + (size_t)e * H;
        float p = 0.f;
        for (int h = lane; h < H; h += 32) p += xr[h] * g[h];
        #pragma unroll
        for (int o = 16; o > 0; o >>= 1) p += __shfl_down_sync(0xffffffffu, p, o);
        if (lane == 0) sc[warp][e] = 1.f / (1.f + expf(-p));
    }
    __syncwarp();
    if (lane == 0) {
        float s[E]; bool used[E];
        #pragma unroll
        for (int e = 0; e < E; e++) { s[e] = sc[warp][e]; used[e] = false; }
        int sel[TOPK]; float w[TOPK]; float sum = 0.f;
        for (int k = 0; k < TOPK; k++) {
            float best = -1e30f; int bi = 0;
            for (int e = 0; e < E; e++) {
                float v = s[e] + bias[e];
                if (!used[e] && v > best) { best = v; bi = e; }
            }
            used[bi] = true; sel[k] = bi; w[k] = s[bi]; sum += s[bi];
        }
        float inv = 1.f / fmaxf(sum, 1e-20f);
        for (int k = 0; k < TOPK; k++) {
            int e = sel[k];
            int pos = atomicAdd(&g_cnt[e], 1);
            g_list[e * T + pos]  = t * TOPK + k;
            g_wlist[e * T + pos] = w[k] * inv;
        }
    }
}

// ============================================================================
// GEMM core macro: loads chunk (A 128x32, B 64x32 fp32 -> bf16 hi/lo smem),
// then 2 k16 steps of 24 mma.sync each (3-term split), acc[2][4][4].
// ============================================================================
#define GEMM_LOOP(NCH, A_LOAD_EXPR, B_LOAD_EXPR)                               \
    for (int c = 0; c < (NCH); c++) {                                          \
        int k0 = c * 32;                                                       \
        __syncthreads();                                                       \
        _Pragma("unroll")                                                      \
        for (int i = 0; i < 4; i++) {                                          \
            float4 v = (A_LOAD_EXPR);                                          \
            store_pair(sm + OFF_AHI, sm + OFF_ALO, ra, kb + i * 4, v);         \
        }                                                                      \
        _Pragma("unroll")                                                      \
        for (int i = 0; i < 2; i++) {                                          \
            float4 v = (B_LOAD_EXPR);                                          \
            store_pair(sm + OFF_BHI, sm + OFF_BLO, rb, kb2 + i * 4, v);        \
        }                                                                      \
        __syncthreads();                                                       \
        _Pragma("unroll")                                                      \
        for (int s = 0; s < 2; s++) {                                          \
            uint32_t ah[2][4], al[2][4], bh[4][2], bl[4][2];                   \
            _Pragma("unroll")                                                  \
            for (int mi = 0; mi < 2; mi++) {                                   \
                uint32_t adr = sAhi + aRowOff + mi * (16 * ASTRIDE) + s * 32;  \
                ldm_x4(ah[mi][0], ah[mi][1], ah[mi][2], ah[mi][3], adr);       \
                ldm_x4(al[mi][0], al[mi][1], al[mi][2], al[mi][3],             \
                       adr + (OFF_ALO - OFF_AHI));                             \
            }                                                                  \
            _Pragma("unroll")                                                  \
            for (int nj = 0; nj < 2; nj++) {                                   \
                uint32_t adr = sBhi + bRowOff + nj * (16 * ASTRIDE) + s * 32;  \
                ldm_x4(bh[2*nj][0], bh[2*nj][1], bh[2*nj+1][0], bh[2*nj+1][1], adr); \
                ldm_x4(bl[2*nj][0], bl[2*nj][1], bl[2*nj+1][0], bl[2*nj+1][1], \
                       adr + (OFF_BLO - OFF_BHI));                             \
            }                                                                  \
            _Pragma("unroll")                                                  \
            for (int mi = 0; mi < 2; mi++)                                     \
                _Pragma("unroll")                                              \
                for (int ni = 0; ni < 4; ni++) {                               \
                    mma_bf16(acc[mi][ni], ah[mi], bh[ni]);                     \
                    mma_bf16(acc[mi][ni], ah[mi], bl[ni]);                     \
                    mma_bf16(acc[mi][ni], al[mi], bh[ni]);                     \
                }                                                              \
        }                                                                      \
    }

// ---------------- GEMM1: gu = rows @ w1^T, fused SiLU*u ----------------------
// CTA tile: 128 rows x 64 B-cols, B col n: even = gate(f0+n/2), odd = up(f0+n/2)
// grid.x = 16 mtiles * 16 ftiles, grid.y = E or 1
__global__ void __launch_bounds__(256) k_mm1(const float* __restrict__ x,
                                             const float* __restrict__ w1base,
                                             int routed) {
    int e  = blockIdx.y;
    int mt = blockIdx.x >> 4;
    int ft = blockIdx.x & 15;
    int M; const int* list; const float* W; float* ACT;
    if (routed) {
        M = g_cnt[e]; list = g_list + e * T;
        W = w1base + (size_t)e * 2 * FF * H;
        ACT = g_act + (size_t)e * T * FF;
    } else {
        M = T; list = nullptr; W = w1base; ACT = g_sact;
    }
    int m0 = mt * 128;
    if (m0 >= M) return;
    int f0 = ft * 32;

    __shared__ __align__(16) char sm[SMEM_TOTAL];
    int tid = threadIdx.x, l = tid & 31, wid = tid >> 5;
    int wm = wid & 3, wn = wid >> 2;

    // loader mappings
    int ra = tid >> 1, kb = (tid & 1) * 16;
    int rb = tid >> 2, kb2 = (tid & 3) * 8;
    bool aval = (m0 + ra) < M;
    const float* aptr = x;
    if (aval) {
        int tok = routed ? (list[m0 + ra] >> 2) : (m0 + ra);
        aptr = x + (size_t)tok * H;
    }
    int fb = f0 + (rb >> 1);
    int wrow = (rb & 1) ? (FF + fb) : fb;
    const float* bptr = W + (size_t)wrow * H;

    uint32_t sAhi = smem_u32(sm) + OFF_AHI;
    uint32_t sBhi = smem_u32(sm) + OFF_BHI;
    uint32_t aRowOff = (wm * 32 + (l & 15)) * ASTRIDE + ((l >> 4) << 4);
    uint32_t bRowOff = (wn * 32 + ((l >> 4) & 1) * 8 + (l & 7)) * ASTRIDE
                     + ((l >> 3) & 1) * 16;

    float acc[2][4][4];
    #pragma unroll
    for (int mi = 0; mi < 2; mi++)
        #pragma unroll
        for (int ni = 0; ni < 4; ni++)
            #pragma unroll
            for (int j = 0; j < 4; j++) acc[mi][ni][j] = 0.f;

    GEMM_LOOP(H / 32,
        (aval ? *(const float4*)(aptr + k0 + kb + i * 4)
              : make_float4(0.f, 0.f, 0.f, 0.f)),
        (*(const float4*)(bptr + k0 + kb2 + i * 4)))

    // epilogue: c0=gate,c1=up (row r), c2,c3 (row r+8)
    #pragma unroll
    for (int mi = 0; mi < 2; mi++) {
        int r0 = m0 + wm * 32 + mi * 16 + (l >> 2);
        int r1 = r0 + 8;
        float* a0 = ACT + (size_t)r0 * FF;
        float* a1 = ACT + (size_t)r1 * FF;
        #pragma unroll
        for (int ni = 0; ni < 4; ni++) {
            int f = f0 + ((wn * 32 + ni * 8 + (l & 3) * 2) >> 1);
            float* c = acc[mi][ni];
            if (r0 < M) a0[f] = silu_mul(c[0], c[1]);
            if (r1 < M) a1[f] = silu_mul(c[2], c[3]);
        }
    }
}

// ---------------- GEMM2: y = act @ w2^T, scaled scatter ----------------------
// CTA tile 128 x 64 H-cols. grid.x = 16 mtiles * 16 htiles, grid.y = E or 1
__global__ void __launch_bounds__(256) k_mm2(const float* __restrict__ w2base,
                                             int routed) {
    int e  = blockIdx.y;
    int mt = blockIdx.x >> 4;
    int ht = blockIdx.x & 15;
    int M; const int* list; const float* wl; const float* A; const float* W;
    if (routed) {
        M = g_cnt[e]; list = g_list + e * T; wl = g_wlist + e * T;
        A = g_act + (size_t)e * T * FF;
        W = w2base + (size_t)e * H * FF;
    } else {
        M = T; list = nullptr; wl = nullptr; A = g_sact; W = w2base;
    }
    int m0 = mt * 128;
    if (m0 >= M) return;
    int n0 = ht * 64;

    __shared__ __align__(16) char sm[SMEM_TOTAL];
    int tid = threadIdx.x, l = tid & 31, wid = tid >> 5;
    int wm = wid & 3, wn = wid >> 2;

    int ra = tid >> 1, kb = (tid & 1) * 16;
    int rb = tid >> 2, kb2 = (tid & 3) * 8;
    int arow = m0 + ra; if (arow >= M) arow = M - 1;  // clamp (stale data ok, rows masked)
    const float* aptr = A + (size_t)arow * FF;
    const float* bptr = W + (size_t)(n0 + rb) * FF;

    uint32_t sAhi = smem_u32(sm) + OFF_AHI;
    uint32_t sBhi = smem_u32(sm) + OFF_BHI;
    uint32_t aRowOff = (wm * 32 + (l & 15)) * ASTRIDE + ((l >> 4) << 4);
    uint32_t bRowOff = (wn * 32 + ((l >> 4) & 1) * 8 + (l & 7)) * ASTRIDE
                     + ((l >> 3) & 1) * 16;

    float acc[2][4][4];
    #pragma unroll
    for (int mi = 0; mi < 2; mi++)
        #pragma unroll
        for (int ni = 0; ni < 4; ni++)
            #pragma unroll
            for (int j = 0; j < 4; j++) acc[mi][ni][j] = 0.f;

    GEMM_LOOP(FF / 32,
        (*(const float4*)(aptr + k0 + kb + i * 4)),
        (*(const float4*)(bptr + k0 + kb2 + i * 4)))

    #pragma unroll
    for (int mi = 0; mi < 2; mi++) {
        int r0 = m0 + wm * 32 + mi * 16 + (l >> 2);
        int r1 = r0 + 8;
        float s0 = 1.f, s1 = 1.f;
        float* o0 = g_sout; float* o1 = g_sout;
        if (routed) {
            if (r0 < M) { s0 = wl[r0]; o0 = g_ybuf + (size_t)list[r0] * H; }
            if (r1 < M) { s1 = wl[r1]; o1 = g_ybuf + (size_t)list[r1] * H; }
        } else {
            o0 = g_sout + (size_t)r0 * H;
            o1 = g_sout + (size_t)r1 * H;
        }
        #pragma unroll
        for (int ni = 0; ni < 4; ni++) {
            int h = n0 + wn * 32 + ni * 8 + (l & 3) * 2;
            float* c = acc[mi][ni];
            if (r0 < M) { o0[h] = s0 * c[0]; o0[h + 1] = s0 * c[1]; }
            if (r1 < M) { o1[h] = s1 * c[2]; o1[h + 1] = s1 * c[3]; }
        }
    }
}

// ---------------- combine ----------------------------------------------------
__global__ void k_combine(float* __restrict__ out) {
    int idx = blockIdx.x * blockDim.x + threadIdx.x;
    if (idx >= T * H) return;
    int t = idx >> 10;
    int h = idx & (H - 1);
    const float* yb = g_ybuf + (size_t)t * TOPK * H + h;
    out[idx] = g_sout[idx] + yb[0] + yb[H] + yb[2 * H] + yb[3 * H];
}

// ---------------- launcher ---------------------------------------------------
extern "C" void kernel_launch(void* const* d_in, const int* in_sizes, int n_in,
                              void* d_out, int out_size) {
    (void)in_sizes; (void)n_in; (void)out_size;
    const float* x    = (const float*)d_in[0];
    const float* gw   = (const float*)d_in[1];
    const float* bias = (const float*)d_in[2];
    const float* w1   = (const float*)d_in[3];
    const float* w2   = (const float*)d_in[4];
    const float* sw1  = (const float*)d_in[5];
    const float* sw2  = (const float*)d_in[6];
    float* out = (float*)d_out;

    k_reset<<<1, 32>>>();
    k_gate<<<T / 4, 128>>>(x, gw, bias);

    k_mm1<<<dim3(16 * 16, E), 256>>>(x, w1, 1);
    k_mm1<<<dim3(16 * 16, 1), 256>>>(x, sw1, 0);

    k_mm2<<<dim3(16 * 16, E), 256>>>(w2, 1);
    k_mm2<<<dim3(16 * 16, 1), 256>>>(sw2, 0);

    k_combine<<<(T * H + 255) / 256, 256>>>(out);
}

// round 4
// speedup vs baseline: 2.0698x; 1.0914x over previous
#include <cuda_runtime.h>
#include <cuda_bf16.h>
#include <math.h>
#include <stdint.h>

#define T 2048
#define H 1024
#define FF 512
#define E 16
#define TOPK 4

// GEMM smem geometry: per stage, A 128 rows x 32 k bf16 (stride 80B) hi+lo,
// B 64 rows x 32 k hi+lo.
#define ASTRIDE 80
#define A_PLANE (128 * ASTRIDE)          // 10240
#define B_PLANE (64 * ASTRIDE)           // 5120
#define STG (2 * A_PLANE + 2 * B_PLANE)  // 30720 per stage
#define SMEM_BYTES (2 * STG)             // 61440 (dynamic)

// ---------------- scratch (static device globals) ---------------------------
__device__ int   g_cnt[E];
__device__ int   g_list[E * T];
__device__ float g_wlist[E * T];
__device__ float g_ybuf[(size_t)T * TOPK * H];
__device__ float g_sout[(size_t)T * H];
// bf16 hi/lo planes
__device__ __nv_bfloat16 g_xhi[(size_t)T * H],            g_xlo[(size_t)T * H];
__device__ __nv_bfloat16 g_w1hi[(size_t)E * 2 * FF * H],  g_w1lo[(size_t)E * 2 * FF * H];
__device__ __nv_bfloat16 g_w2hi[(size_t)E * H * FF],      g_w2lo[(size_t)E * H * FF];
__device__ __nv_bfloat16 g_s1hi[(size_t)2 * FF * H],      g_s1lo[(size_t)2 * FF * H];
__device__ __nv_bfloat16 g_s2hi[(size_t)H * FF],          g_s2lo[(size_t)H * FF];
__device__ __nv_bfloat16 g_ahi[(size_t)E * T * FF],       g_alo[(size_t)E * T * FF];
__device__ __nv_bfloat16 g_sahi[(size_t)T * FF],          g_salo[(size_t)T * FF];

// ---------------- helpers ----------------------------------------------------
__device__ __forceinline__ uint32_t smem_u32(const void* p) {
    uint32_t a;
    asm("{ .reg .u64 t; cvta.to.shared.u64 t, %1; cvt.u32.u64 %0, t; }"
        : "=r"(a) : "l"(p));
    return a;
}
__device__ __forceinline__ void ldm_x4(uint32_t& r0, uint32_t& r1,
                                       uint32_t& r2, uint32_t& r3, uint32_t a) {
    asm volatile("ldmatrix.sync.aligned.m8n8.x4.shared.b16 {%0,%1,%2,%3}, [%4];"
                 : "=r"(r0), "=r"(r1), "=r"(r2), "=r"(r3) : "r"(a));
}
__device__ __forceinline__ void mma_bf16(float* c, const uint32_t* a, const uint32_t* b) {
    asm volatile(
        "mma.sync.aligned.m16n8k16.row.col.f32.bf16.bf16.f32 "
        "{%0,%1,%2,%3}, {%4,%5,%6,%7}, {%8,%9}, {%0,%1,%2,%3};"
        : "+f"(c[0]), "+f"(c[1]), "+f"(c[2]), "+f"(c[3])
        : "r"(a[0]), "r"(a[1]), "r"(a[2]), "r"(a[3]), "r"(b[0]), "r"(b[1]));
}
#define CP16(dst, src) \
    asm volatile("cp.async.cg.shared.global [%0], [%1], 16;" :: "r"(dst), "l"(src))
#define CP_COMMIT() asm volatile("cp.async.commit_group;")
#define CP_WAIT1() asm volatile("cp.async.wait_group 1;")
#define CP_WAIT0() asm volatile("cp.async.wait_group 0;")

__device__ __forceinline__ float silu_mul(float g, float u) {
    return g / (1.f + expf(-g)) * u;
}

// ---------------- reset ------------------------------------------------------
__global__ void k_reset() {
    if (threadIdx.x < E) g_cnt[threadIdx.x] = 0;
}

// ---------------- fp32 -> bf16 hi/lo conversion -------------------------------
__global__ void k_conv(const float* __restrict__ in, int n, int id) {
    int i = (blockIdx.x * blockDim.x + threadIdx.x) * 4;
    if (i >= n) return;
    __nv_bfloat16 *hi, *lo;
    switch (id) {
        case 0: hi = g_xhi;  lo = g_xlo;  break;
        case 1: hi = g_w1hi; lo = g_w1lo; break;
        case 2: hi = g_w2hi; lo = g_w2lo; break;
        case 3: hi = g_s1hi; lo = g_s1lo; break;
        default: hi = g_s2hi; lo = g_s2lo; break;
    }
    float4 v = *(const float4*)(in + i);
    __nv_bfloat16 hx = __float2bfloat16(v.x), hy = __float2bfloat16(v.y);
    __nv_bfloat16 hz = __float2bfloat16(v.z), hw = __float2bfloat16(v.w);
    __nv_bfloat162 h0; h0.x = hx; h0.y = hy;
    __nv_bfloat162 h1; h1.x = hz; h1.y = hw;
    __nv_bfloat162 l0, l1;
    l0.x = __float2bfloat16(v.x - __bfloat162float(hx));
    l0.y = __float2bfloat16(v.y - __bfloat162float(hy));
    l1.x = __float2bfloat16(v.z - __bfloat162float(hz));
    l1.y = __float2bfloat16(v.w - __bfloat162float(hw));
    ((__nv_bfloat162*)(hi + i))[0] = h0;
    ((__nv_bfloat162*)(hi + i))[1] = h1;
    ((__nv_bfloat162*)(lo + i))[0] = l0;
    ((__nv_bfloat162*)(lo + i))[1] = l1;
}

// ---------------- gating -----------------------------------------------------
__global__ void k_gate(const float* __restrict__ x,
                       const float* __restrict__ gw,
                       const float* __restrict__ bias) {
    int warp = threadIdx.x >> 5;
    int lane = threadIdx.x & 31;
    int t = blockIdx.x * 4 + warp;
    if (t >= T) return;
    __shared__ float sc[4][E];
    const float* xr = x + (size_t)t * H;
    for (int e = 0; e < E; e++) {
        const float* g = gw + (size_t)e * H;
        float p = 0.f;
        for (int h = lane * 4; h < H; h += 128) {
            float4 xv = *(const float4*)(xr + h);
            float4 gv = *(const float4*)(g + h);
            p += xv.x * gv.x + xv.y * gv.y + xv.z * gv.z + xv.w * gv.w;
        }
        #pragma unroll
        for (int o = 16; o > 0; o >>= 1) p += __shfl_down_sync(0xffffffffu, p, o);
        if (lane == 0) sc[warp][e] = 1.f / (1.f + expf(-p));
    }
    __syncwarp();
    if (lane == 0) {
        float s[E]; bool used[E];
        #pragma unroll
        for (int e = 0; e < E; e++) { s[e] = sc[warp][e]; used[e] = false; }
        int sel[TOPK]; float w[TOPK]; float sum = 0.f;
        for (int k = 0; k < TOPK; k++) {
            float best = -1e30f; int bi = 0;
            for (int e = 0; e < E; e++) {
                float v = s[e] + bias[e];
                if (!used[e] && v > best) { best = v; bi = e; }
            }
            used[bi] = true; sel[k] = bi; w[k] = s[bi]; sum += s[bi];
        }
        float inv = 1.f / fmaxf(sum, 1e-20f);
        for (int k = 0; k < TOPK; k++) {
            int e = sel[k];
            int pos = atomicAdd(&g_cnt[e], 1);
            g_list[e * T + pos]  = t * TOPK + k;
            g_wlist[e * T + pos] = w[k] * inv;
        }
    }
}

// ============================================================================
// shared GEMM pieces
// ============================================================================
// loader: per thread, A: rows(tid>>1) 2 chunks x hi/lo; B: row(tid>>2) 1 chunk x hi/lo
#define LOAD_STAGE(st, k0)                                                     \
    do {                                                                       \
        uint32_t sb = (st) * STG;                                              \
        CP16(aDstH + sb,      aHsrc + (k0));                                   \
        CP16(aDstH + sb + 16, aHsrc + (k0) + 8);                               \
        CP16(aDstL + sb,      aLsrc + (k0));                                   \
        CP16(aDstL + sb + 16, aLsrc + (k0) + 8);                               \
        CP16(bDstH + sb,      bHsrc + (k0));                                   \
        CP16(bDstL + sb,      bLsrc + (k0));                                   \
        CP_COMMIT();                                                           \
    } while (0)

#define COMPUTE_STAGE(st)                                                      \
    do {                                                                       \
        uint32_t sb = (st) * STG;                                              \
        _Pragma("unroll")                                                      \
        for (int s = 0; s < 2; s++) {                                          \
            uint32_t ah[2][4], al[2][4], bh[4][2], bl[4][2];                   \
            _Pragma("unroll")                                                  \
            for (int mi = 0; mi < 2; mi++) {                                   \
                uint32_t adr = sA + sb + aRowOff + mi * (16 * ASTRIDE) + s * 32; \
                ldm_x4(ah[mi][0], ah[mi][1], ah[mi][2], ah[mi][3], adr);       \
                ldm_x4(al[mi][0], al[mi][1], al[mi][2], al[mi][3], adr + A_PLANE); \
            }                                                                  \
            _Pragma("unroll")                                                  \
            for (int nj = 0; nj < 2; nj++) {                                   \
                uint32_t adr = sB + sb + bRowOff + nj * (16 * ASTRIDE) + s * 32; \
                ldm_x4(bh[2*nj][0], bh[2*nj][1], bh[2*nj+1][0], bh[2*nj+1][1], adr); \
                ldm_x4(bl[2*nj][0], bl[2*nj][1], bl[2*nj+1][0], bl[2*nj+1][1], adr + B_PLANE); \
            }                                                                  \
            _Pragma("unroll")                                                  \
            for (int mi = 0; mi < 2; mi++)                                     \
                _Pragma("unroll")                                              \
                for (int ni = 0; ni < 4; ni++) {                               \
                    mma_bf16(acc[mi][ni], ah[mi], bh[ni]);                     \
                    mma_bf16(acc[mi][ni], ah[mi], bl[ni]);                     \
                    mma_bf16(acc[mi][ni], al[mi], bh[ni]);                     \
                }                                                              \
        }                                                                      \
    } while (0)

#define GEMM_PIPE(NCH)                                                         \
    LOAD_STAGE(0, 0);                                                          \
    for (int c = 0; c < (NCH); c++) {                                          \
        if (c + 1 < (NCH)) { LOAD_STAGE((c + 1) & 1, (c + 1) * 32); CP_WAIT1(); } \
        else               { CP_WAIT0(); }                                     \
        __syncthreads();                                                       \
        COMPUTE_STAGE(c & 1);                                                  \
        __syncthreads();                                                       \
    }

// ---------------- GEMM1: gu = rows @ w1^T (interleaved gate/up), SiLU fused --
// grid.x = 16 mtiles * 16 ftiles; grid.y = E+1 (y==E -> shared expert)
__global__ void __launch_bounds__(256) k_mm1() {
    int e  = blockIdx.y;
    int mt = blockIdx.x >> 4;
    int ft = blockIdx.x & 15;
    bool sh = (e == E);
    int M; const int* list = nullptr;
    const __nv_bfloat16 *Whi, *Wlo; __nv_bfloat16 *AHI, *ALO;
    if (!sh) {
        M = g_cnt[e]; list = g_list + e * T;
        Whi = g_w1hi + (size_t)e * 2 * FF * H;
        Wlo = g_w1lo + (size_t)e * 2 * FF * H;
        AHI = g_ahi + (size_t)e * T * FF;
        ALO = g_alo + (size_t)e * T * FF;
    } else {
        M = T; Whi = g_s1hi; Wlo = g_s1lo; AHI = g_sahi; ALO = g_salo;
    }
    int m0 = mt * 128;
    if (m0 >= M) return;
    int f0 = ft * 32;

    extern __shared__ __align__(16) char sm[];
    int tid = threadIdx.x, l = tid & 31, wid = tid >> 5;
    int wm = wid & 3, wn = wid >> 2;

    // loader src/dst
    int ra = tid >> 1, ca = (tid & 1) * 16;
    int arow = m0 + ra; if (arow >= M) arow = M - 1;
    int tok = sh ? arow : (list[arow] >> 2);
    const __nv_bfloat16* aHsrc = g_xhi + (size_t)tok * H + ca;
    const __nv_bfloat16* aLsrc = g_xlo + (size_t)tok * H + ca;
    int rb = tid >> 2, cbv = (tid & 3) * 8;
    int fb = f0 + (rb >> 1);
    int wrow = (rb & 1) ? (FF + fb) : fb;
    const __nv_bfloat16* bHsrc = Whi + (size_t)wrow * H + cbv;
    const __nv_bfloat16* bLsrc = Wlo + (size_t)wrow * H + cbv;

    uint32_t sA = smem_u32(sm);
    uint32_t sB = sA + 2 * A_PLANE;
    uint32_t aDstH = sA + ra * ASTRIDE + ca * 2;
    uint32_t aDstL = aDstH + A_PLANE;
    uint32_t bDstH = sB + rb * ASTRIDE + cbv * 2;
    uint32_t bDstL = bDstH + B_PLANE;

    uint32_t aRowOff = (wm * 32 + (l & 15)) * ASTRIDE + ((l >> 4) << 4);
    uint32_t bRowOff = (wn * 32 + ((l >> 4) & 1) * 8 + (l & 7)) * ASTRIDE
                     + ((l >> 3) & 1) * 16;

    float acc[2][4][4];
    #pragma unroll
    for (int mi = 0; mi < 2; mi++)
        #pragma unroll
        for (int ni = 0; ni < 4; ni++)
            #pragma unroll
            for (int j = 0; j < 4; j++) acc[mi][ni][j] = 0.f;

    GEMM_PIPE(H / 32)

    // epilogue: (c0,c1)=(gate,up) row r0; (c2,c3) row r1 -> bf16 hi/lo act
    #pragma unroll
    for (int mi = 0; mi < 2; mi++) {
        int r0 = m0 + wm * 32 + mi * 16 + (l >> 2);
        int r1 = r0 + 8;
        #pragma unroll
        for (int ni = 0; ni < 4; ni++) {
            int f = f0 + ((wn * 32 + ni * 8 + (l & 3) * 2) >> 1);
            float* c = acc[mi][ni];
            if (r0 < M) {
                float a = silu_mul(c[0], c[1]);
                __nv_bfloat16 h = __float2bfloat16(a);
                AHI[(size_t)r0 * FF + f] = h;
                ALO[(size_t)r0 * FF + f] = __float2bfloat16(a - __bfloat162float(h));
            }
            if (r1 < M) {
                float a = silu_mul(c[2], c[3]);
                __nv_bfloat16 h = __float2bfloat16(a);
                AHI[(size_t)r1 * FF + f] = h;
                ALO[(size_t)r1 * FF + f] = __float2bfloat16(a - __bfloat162float(h));
            }
        }
    }
}

// ---------------- GEMM2: y = act @ w2^T, scaled scatter ----------------------
// grid.x = 16 mtiles * 16 htiles; grid.y = E+1
__global__ void __launch_bounds__(256) k_mm2() {
    int e  = blockIdx.y;
    int mt = blockIdx.x >> 4;
    int ht = blockIdx.x & 15;
    bool sh = (e == E);
    int M; const int* list = nullptr; const float* wl = nullptr;
    const __nv_bfloat16 *Ahi, *Alo, *Whi, *Wlo;
    if (!sh) {
        M = g_cnt[e]; list = g_list + e * T; wl = g_wlist + e * T;
        Ahi = g_ahi + (size_t)e * T * FF;  Alo = g_alo + (size_t)e * T * FF;
        Whi = g_w2hi + (size_t)e * H * FF; Wlo = g_w2lo + (size_t)e * H * FF;
    } else {
        M = T; Ahi = g_sahi; Alo = g_salo; Whi = g_s2hi; Wlo = g_s2lo;
    }
    int m0 = mt * 128;
    if (m0 >= M) return;
    int n0 = ht * 64;

    extern __shared__ __align__(16) char sm[];
    int tid = threadIdx.x, l = tid & 31, wid = tid >> 5;
    int wm = wid & 3, wn = wid >> 2;

    int ra = tid >> 1, ca = (tid & 1) * 16;
    int arow = m0 + ra; if (arow >= M) arow = M - 1;
    const __nv_bfloat16* aHsrc = Ahi + (size_t)arow * FF + ca;
    const __nv_bfloat16* aLsrc = Alo + (size_t)arow * FF + ca;
    int rb = tid >> 2, cbv = (tid & 3) * 8;
    const __nv_bfloat16* bHsrc = Whi + (size_t)(n0 + rb) * FF + cbv;
    const __nv_bfloat16* bLsrc = Wlo + (size_t)(n0 + rb) * FF + cbv;

    uint32_t sA = smem_u32(sm);
    uint32_t sB = sA + 2 * A_PLANE;
    uint32_t aDstH = sA + ra * ASTRIDE + ca * 2;
    uint32_t aDstL = aDstH + A_PLANE;
    uint32_t bDstH = sB + rb * ASTRIDE + cbv * 2;
    uint32_t bDstL = bDstH + B_PLANE;

    uint32_t aRowOff = (wm * 32 + (l & 15)) * ASTRIDE + ((l >> 4) << 4);
    uint32_t bRowOff = (wn * 32 + ((l >> 4) & 1) * 8 + (l & 7)) * ASTRIDE
                     + ((l >> 3) & 1) * 16;

    float acc[2][4][4];
    #pragma unroll
    for (int mi = 0; mi < 2; mi++)
        #pragma unroll
        for (int ni = 0; ni < 4; ni++)
            #pragma unroll
            for (int j = 0; j < 4; j++) acc[mi][ni][j] = 0.f;

    GEMM_PIPE(FF / 32)

    #pragma unroll
    for (int mi = 0; mi < 2; mi++) {
        int r0 = m0 + wm * 32 + mi * 16 + (l >> 2);
        int r1 = r0 + 8;
        float s0 = 1.f, s1 = 1.f;
        float* o0 = g_sout; float* o1 = g_sout;
        if (!sh) {
            if (r0 < M) { s0 = wl[r0]; o0 = g_ybuf + (size_t)list[r0] * H; }
            if (r1 < M) { s1 = wl[r1]; o1 = g_ybuf + (size_t)list[r1] * H; }
        } else {
            o0 = g_sout + (size_t)r0 * H;
            o1 = g_sout + (size_t)r1 * H;
        }
        #pragma unroll
        for (int ni = 0; ni < 4; ni++) {
            int h = n0 + wn * 32 + ni * 8 + (l & 3) * 2;
            float* c = acc[mi][ni];
            if (r0 < M) { o0[h] = s0 * c[0]; o0[h + 1] = s0 * c[1]; }
            if (r1 < M) { o1[h] = s1 * c[2]; o1[h + 1] = s1 * c[3]; }
        }
    }
}

// ---------------- combine ----------------------------------------------------
__global__ void k_combine(float* __restrict__ out) {
    int idx = blockIdx.x * blockDim.x + threadIdx.x;
    if (idx >= T * H) return;
    int t = idx >> 10;
    int h = idx & (H - 1);
    const float* yb = g_ybuf + (size_t)t * TOPK * H + h;
    out[idx] = g_sout[idx] + yb[0] + yb[H] + yb[2 * H] + yb[3 * H];
}

// ---------------- launcher ---------------------------------------------------
extern "C" void kernel_launch(void* const* d_in, const int* in_sizes, int n_in,
                              void* d_out, int out_size) {
    (void)in_sizes; (void)n_in; (void)out_size;
    const float* x    = (const float*)d_in[0];
    const float* gw   = (const float*)d_in[1];
    const float* bias = (const float*)d_in[2];
    const float* w1   = (const float*)d_in[3];
    const float* w2   = (const float*)d_in[4];
    const float* sw1  = (const float*)d_in[5];
    const float* sw2  = (const float*)d_in[6];
    float* out = (float*)d_out;

    cudaFuncSetAttribute(k_mm1, cudaFuncAttributeMaxDynamicSharedMemorySize, SMEM_BYTES);
    cudaFuncSetAttribute(k_mm2, cudaFuncAttributeMaxDynamicSharedMemorySize, SMEM_BYTES);

    k_reset<<<1, 32>>>();
    k_gate<<<T / 4, 128>>>(x, gw, bias);

    auto conv = [](const float* p, int n, int id) {
        k_conv<<<(n / 4 + 255) / 256, 256>>>(p, n, id);
    };
    conv(x,   T * H, 0);
    conv(w1,  E * 2 * FF * H, 1);
    conv(w2,  E * H * FF, 2);
    conv(sw1, 2 * FF * H, 3);
    conv(sw2, H * FF, 4);

    k_mm1<<<dim3(16 * 16, E + 1), 256, SMEM_BYTES>>>();
    k_mm2<<<dim3(16 * 16, E + 1), 256, SMEM_BYTES>>>();

    k_combine<<<(T * H + 255) / 256, 256>>>(out);
}